// round 13
// baseline (speedup 1.0000x reference)
#include <cuda_runtime.h>

// Problem constants: preds/target [B=8, C=21, H=512, W=512] float32.
// Base: session winner (57.28-57.38us verified; __ldcs, 2 kernels, PDL).
// R12 delta: 256-bit global loads (ld.global.cs.v8.f32, sm_100a PTX) —
// halves LDG count and L1tex wavefronts per byte. Loop re-indexed in
// float8 units; mapping/structure otherwise identical to the winner.
#define NB 8
#define NC 21
#define HW (512 * 512)            // 262144 floats per (b,c) slab
#define HW8 (HW / 8)              // 32768 float8 per slab
#define CHUNKS_PER_SLAB 8
#define TPB 256
#define VEC_PER_THREAD (HW8 / CHUNKS_PER_SLAB / TPB)   // 16
#define BLOCKS_PER_CLASS (NB * CHUNKS_PER_SLAB)        // 64
#define GRID (NC * BLOCKS_PER_CLASS)                   // 1344

// Scratch accumulators (no cudaMalloc allowed — __device__ globals).
// Zero-initialized at module load; jaccard_final_kernel re-zeroes them after
// every read, so each replay of the captured graph starts from zero.
__device__ int g_inter[NC];
__device__ int g_pred[NC];
__device__ int g_targ[NC];

// 256-bit streaming load (evict-first). Requires 32B-aligned address;
// sm_100a-only PTX (.v8.f32 vector ld).
__device__ __forceinline__ void ldg256_cs(const float* __restrict__ p, float r[8]) {
    asm volatile(
        "ld.global.cs.v8.f32 {%0,%1,%2,%3,%4,%5,%6,%7}, [%8];"
        : "=f"(r[0]), "=f"(r[1]), "=f"(r[2]), "=f"(r[3]),
          "=f"(r[4]), "=f"(r[5]), "=f"(r[6]), "=f"(r[7])
        : "l"(p));
}

__global__ __launch_bounds__(TPB, 1)
void jaccard_count_kernel(const float* __restrict__ preds,
                          const float* __restrict__ targ) {
    const int blk   = blockIdx.x;
    const int c     = blk / BLOCKS_PER_CLASS;
    const int s     = blk % BLOCKS_PER_CLASS;
    const int b     = s / CHUNKS_PER_SLAB;
    const int chunk = s % CHUNKS_PER_SLAB;

    // Base offset of this block's contiguous region, in float8 units.
    // Per-thread addresses are 32B-aligned: (base_f8 * 8 floats) * 4B.
    const size_t base_f8 = (size_t)b * (NC * (size_t)HW8)
                         + (size_t)c * HW8
                         + (size_t)chunk * (HW8 / CHUNKS_PER_SLAB)
                         + threadIdx.x;

    int inter = 0, ps = 0, ts = 0;

#pragma unroll 4
    for (int j = 0; j < VEC_PER_THREAD; ++j) {
        const size_t fidx = (base_f8 + (size_t)j * TPB) * 8;
        float p[8], t[8];
        ldg256_cs(preds + fidx, p);
        ldg256_cs(targ  + fidx, t);

#pragma unroll
        for (int e = 0; e < 8; ++e) {
            const int pm = (p[e] >= 0.5f);
            const int tm = (t[e] == 1.0f);
            ps    += pm;
            ts    += tm;
            inter += pm & tm;
        }
    }

    // Warp reduction.
#pragma unroll
    for (int off = 16; off > 0; off >>= 1) {
        inter += __shfl_down_sync(0xffffffffu, inter, off);
        ps    += __shfl_down_sync(0xffffffffu, ps,    off);
        ts    += __shfl_down_sync(0xffffffffu, ts,    off);
    }

    __shared__ int s_i[TPB / 32], s_p[TPB / 32], s_t[TPB / 32];
    const int w = threadIdx.x >> 5;
    const int l = threadIdx.x & 31;
    if (l == 0) { s_i[w] = inter; s_p[w] = ps; s_t[w] = ts; }
    __syncthreads();

    if (threadIdx.x == 0) {
        int I = 0, P = 0, T = 0;
#pragma unroll
        for (int k = 0; k < TPB / 32; ++k) { I += s_i[k]; P += s_p[k]; T += s_t[k]; }
        atomicAdd(&g_inter[c], I);
        atomicAdd(&g_pred[c],  P);
        atomicAdd(&g_targ[c],  T);
        // PDL: signal the dependent (final) launch; pre-trigger writes are
        // visible after cudaGridDependencySynchronize() in the secondary.
        cudaTriggerProgrammaticLaunchCompletion();
    }
}

__global__ void jaccard_final_kernel(float* __restrict__ out) {
    // Launched with programmatic stream serialization: block until the count
    // kernel's trigger fires.
    cudaGridDependencySynchronize();

    int c = threadIdx.x;
    if (c < NC) {
        const float inter = (float)g_inter[c];
        const float uni   = (float)g_pred[c] + (float)g_targ[c] - inter;
        out[c] = (uni == 0.0f) ? __int_as_float(0x7fc00000)   // NaN
                               : inter / fmaxf(uni, 1.0f);
        // Reset counters for the next graph replay (final -> next count is
        // NOT a PDL pair; normal stream order fully serializes it).
        g_inter[c] = 0;
        g_pred[c]  = 0;
        g_targ[c]  = 0;
    }
}

extern "C" void kernel_launch(void* const* d_in, const int* in_sizes, int n_in,
                              void* d_out, int out_size) {
    const float* preds = (const float*)d_in[0];
    const float* targ  = (const float*)d_in[1];
    float* out         = (float*)d_out;

    jaccard_count_kernel<<<GRID, TPB>>>(preds, targ);

    // Secondary launch with PDL opt-in: overlaps its setup with the count
    // kernel's tail on the same (default) stream.
    cudaLaunchConfig_t cfg = {};
    cfg.gridDim  = dim3(1, 1, 1);
    cfg.blockDim = dim3(32, 1, 1);
    cfg.dynamicSmemBytes = 0;
    cfg.stream = 0;  // same stream as the <<<>>> launch above
    cudaLaunchAttribute attrs[1];
    attrs[0].id = cudaLaunchAttributeProgrammaticStreamSerialization;
    attrs[0].val.programmaticStreamSerializationAllowed = 1;
    cfg.attrs = attrs;
    cfg.numAttrs = 1;
    cudaLaunchKernelEx(&cfg, jaccard_final_kernel, out);
}

// round 14
// speedup vs baseline: 1.0211x; 1.0211x over previous
#include <cuda_runtime.h>

// Problem constants: preds/target [B=8, C=21, H=512, W=512] float32.
// FINAL KERNEL — session converged (R1-R12, 11 measured variants).
//
// Verified 57.28 / 57.34 / 57.34 us (rel_err 0.0) across three benches.
// Count kernel streams 352 MB at ~6.15 TB/s; established as the device
// plateau by six falsified levers: occupancy (33%/66%), fusion, grid size,
// access pattern, block->address mapping, and 128b->256b loads (all nil or
// regression). Wins: __ldcs evict-first (-1.0us), zero-node elimination
// (-0.5us), PDL-overlapped final node (~-0.1us).
#define NB 8
#define NC 21
#define HW (512 * 512)            // 262144 floats per (b,c) slab
#define HW4 (HW / 4)              // 65536 float4 per slab
#define CHUNKS_PER_SLAB 8
#define TPB 256
#define VEC_PER_THREAD (HW4 / CHUNKS_PER_SLAB / TPB)   // 32
#define BLOCKS_PER_CLASS (NB * CHUNKS_PER_SLAB)        // 64
#define GRID (NC * BLOCKS_PER_CLASS)                   // 1344

// Scratch accumulators (no cudaMalloc allowed — __device__ globals).
// Zero-initialized at module load; jaccard_final_kernel re-zeroes them after
// every read, so each replay of the captured graph starts from zero.
__device__ int g_inter[NC];
__device__ int g_pred[NC];
__device__ int g_targ[NC];

__global__ __launch_bounds__(TPB, 1)
void jaccard_count_kernel(const float4* __restrict__ preds,
                          const float4* __restrict__ targ) {
    const int blk   = blockIdx.x;
    const int c     = blk / BLOCKS_PER_CLASS;
    const int s     = blk % BLOCKS_PER_CLASS;
    const int b     = s / CHUNKS_PER_SLAB;
    const int chunk = s % CHUNKS_PER_SLAB;

    // Base offset of this block's contiguous region, in float4 units.
    const size_t base = (size_t)b * (NC * (size_t)HW4)
                      + (size_t)c * HW4
                      + (size_t)chunk * (HW4 / CHUNKS_PER_SLAB)
                      + threadIdx.x;

    int inter = 0, ps = 0, ts = 0;

#pragma unroll 8
    for (int j = 0; j < VEC_PER_THREAD; ++j) {
        const size_t idx = base + (size_t)j * TPB;
        // Streaming loads (evict-first): zero reuse, keep L2 pressure minimal.
        const float4 p = __ldcs(preds + idx);
        const float4 t = __ldcs(targ + idx);

        const int pm0 = (p.x >= 0.5f), pm1 = (p.y >= 0.5f);
        const int pm2 = (p.z >= 0.5f), pm3 = (p.w >= 0.5f);
        const int tm0 = (t.x == 1.0f), tm1 = (t.y == 1.0f);
        const int tm2 = (t.z == 1.0f), tm3 = (t.w == 1.0f);

        ps    += pm0 + pm1 + pm2 + pm3;
        ts    += tm0 + tm1 + tm2 + tm3;
        inter += (pm0 & tm0) + (pm1 & tm1) + (pm2 & tm2) + (pm3 & tm3);
    }

    // Warp reduction.
#pragma unroll
    for (int off = 16; off > 0; off >>= 1) {
        inter += __shfl_down_sync(0xffffffffu, inter, off);
        ps    += __shfl_down_sync(0xffffffffu, ps,    off);
        ts    += __shfl_down_sync(0xffffffffu, ts,    off);
    }

    __shared__ int s_i[TPB / 32], s_p[TPB / 32], s_t[TPB / 32];
    const int w = threadIdx.x >> 5;
    const int l = threadIdx.x & 31;
    if (l == 0) { s_i[w] = inter; s_p[w] = ps; s_t[w] = ts; }
    __syncthreads();

    if (threadIdx.x == 0) {
        int I = 0, P = 0, T = 0;
#pragma unroll
        for (int k = 0; k < TPB / 32; ++k) { I += s_i[k]; P += s_p[k]; T += s_t[k]; }
        atomicAdd(&g_inter[c], I);
        atomicAdd(&g_pred[c],  P);
        atomicAdd(&g_targ[c],  T);
        // PDL: this block's contribution is done — signal the dependent
        // launch. Pre-trigger writes are visible to the secondary after
        // cudaGridDependencySynchronize().
        cudaTriggerProgrammaticLaunchCompletion();
    }
}

__global__ void jaccard_final_kernel(float* __restrict__ out) {
    // Launched with programmatic stream serialization: we may start while the
    // count kernel is still draining. Block here until its trigger fires.
    cudaGridDependencySynchronize();

    int c = threadIdx.x;
    if (c < NC) {
        const float inter = (float)g_inter[c];
        const float uni   = (float)g_pred[c] + (float)g_targ[c] - inter;
        out[c] = (uni == 0.0f) ? __int_as_float(0x7fc00000)   // NaN
                               : inter / fmaxf(uni, 1.0f);
        // Reset counters for the next graph replay (final -> next count is
        // NOT a PDL pair; normal stream order fully serializes it).
        g_inter[c] = 0;
        g_pred[c]  = 0;
        g_targ[c]  = 0;
    }
}

extern "C" void kernel_launch(void* const* d_in, const int* in_sizes, int n_in,
                              void* d_out, int out_size) {
    const float4* preds = (const float4*)d_in[0];
    const float4* targ  = (const float4*)d_in[1];
    float* out          = (float*)d_out;

    jaccard_count_kernel<<<GRID, TPB>>>(preds, targ);

    // Secondary launch with PDL opt-in: overlaps its setup with the count
    // kernel's tail on the same (default) stream.
    cudaLaunchConfig_t cfg = {};
    cfg.gridDim  = dim3(1, 1, 1);
    cfg.blockDim = dim3(32, 1, 1);
    cfg.dynamicSmemBytes = 0;
    cfg.stream = 0;  // same stream as the <<<>>> launch above
    cudaLaunchAttribute attrs[1];
    attrs[0].id = cudaLaunchAttributeProgrammaticStreamSerialization;
    attrs[0].val.programmaticStreamSerializationAllowed = 1;
    cfg.attrs = attrs;
    cfg.numAttrs = 1;
    cudaLaunchKernelEx(&cfg, jaccard_final_kernel, out);
}